// round 1
// baseline (speedup 1.0000x reference)
#include <cuda_runtime.h>
#include <cuda_bf16.h>
#include <math.h>

// Problem constants
#define B_ 16
#define T_ 2048
#define C_ 1024
#define H_ 64
#define M_ (B_ * T_)   // 32768 rows for projection GEMM

// Scratch for projected Q, K, V  (8 MB each; static device arrays — no allocs)
__device__ float g_q[(size_t)M_ * H_];
__device__ float g_k[(size_t)M_ * H_];
__device__ float g_v[(size_t)M_ * H_];

// ---------------------------------------------------------------------------
// Projection GEMM:  O[m,h] = sum_c x[m,c] * W[c,h]
// M=32768, K=1024, N=64.  BM=64, BN=64, BK=32.  128 threads, 4x8 microtile.
// gridDim.y = 3 selects (w_q, w_k, w_v) -> (g_q, g_k, g_v).
// ---------------------------------------------------------------------------
__global__ __launch_bounds__(128) void proj_kernel(
    const float* __restrict__ x,
    const float* __restrict__ wq,
    const float* __restrict__ wk,
    const float* __restrict__ wv)
{
    const float* W;
    float* O;
    if (blockIdx.y == 0)      { W = wq; O = g_q; }
    else if (blockIdx.y == 1) { W = wk; O = g_k; }
    else                      { W = wv; O = g_v; }

    __shared__ float xs[64][33];   // [m][k], pad 33 -> conflict-free STS & 2-way LDS
    __shared__ float ws[32][64];   // [k][h]

    const int tid = threadIdx.x;
    const int ty  = tid >> 3;      // 0..15 -> rows ty*4..ty*4+3
    const int tx  = tid & 7;       // 0..7  -> cols tx*8..tx*8+7
    const int m0  = blockIdx.x * 64;

    float acc[4][8];
#pragma unroll
    for (int i = 0; i < 4; i++)
#pragma unroll
        for (int j = 0; j < 8; j++) acc[i][j] = 0.0f;

    for (int k0 = 0; k0 < C_; k0 += 32) {
        // Load x tile 64x32 (coalesced float4 reads; scalar conflict-free STS)
#pragma unroll
        for (int q = 0; q < 4; q++) {
            int i  = tid + 128 * q;        // 0..511 float4 slots
            int r  = i >> 3;               // row 0..63
            int kq = i & 7;                // float4 within row
            float4 v = *(const float4*)(x + (size_t)(m0 + r) * C_ + k0 + kq * 4);
            xs[r][kq * 4 + 0] = v.x;
            xs[r][kq * 4 + 1] = v.y;
            xs[r][kq * 4 + 2] = v.z;
            xs[r][kq * 4 + 3] = v.w;
        }
        // Load w tile 32x64 (direct float4 copy)
#pragma unroll
        for (int q = 0; q < 4; q++) {
            int i  = tid + 128 * q;        // 0..511 float4 slots
            int kr = i >> 4;               // 0..31
            int cq = i & 15;               // float4 within 64-col row
            *(float4*)(&ws[kr][cq * 4]) =
                *(const float4*)(W + (size_t)(k0 + kr) * H_ + cq * 4);
        }
        __syncthreads();

#pragma unroll
        for (int kk = 0; kk < 32; kk++) {
            float a0 = xs[ty * 4 + 0][kk];
            float a1 = xs[ty * 4 + 1][kk];
            float a2 = xs[ty * 4 + 2][kk];
            float a3 = xs[ty * 4 + 3][kk];
            float4 b0 = *(const float4*)(&ws[kk][tx * 8]);
            float4 b1 = *(const float4*)(&ws[kk][tx * 8 + 4]);

            acc[0][0] += a0 * b0.x; acc[0][1] += a0 * b0.y;
            acc[0][2] += a0 * b0.z; acc[0][3] += a0 * b0.w;
            acc[0][4] += a0 * b1.x; acc[0][5] += a0 * b1.y;
            acc[0][6] += a0 * b1.z; acc[0][7] += a0 * b1.w;

            acc[1][0] += a1 * b0.x; acc[1][1] += a1 * b0.y;
            acc[1][2] += a1 * b0.z; acc[1][3] += a1 * b0.w;
            acc[1][4] += a1 * b1.x; acc[1][5] += a1 * b1.y;
            acc[1][6] += a1 * b1.z; acc[1][7] += a1 * b1.w;

            acc[2][0] += a2 * b0.x; acc[2][1] += a2 * b0.y;
            acc[2][2] += a2 * b0.z; acc[2][3] += a2 * b0.w;
            acc[2][4] += a2 * b1.x; acc[2][5] += a2 * b1.y;
            acc[2][6] += a2 * b1.z; acc[2][7] += a2 * b1.w;

            acc[3][0] += a3 * b0.x; acc[3][1] += a3 * b0.y;
            acc[3][2] += a3 * b0.z; acc[3][3] += a3 * b0.w;
            acc[3][4] += a3 * b1.x; acc[3][5] += a3 * b1.y;
            acc[3][6] += a3 * b1.z; acc[3][7] += a3 * b1.w;
        }
        __syncthreads();
    }

#pragma unroll
    for (int i = 0; i < 4; i++) {
        size_t row = (size_t)(m0 + ty * 4 + i);
        float4 o0 = make_float4(acc[i][0], acc[i][1], acc[i][2], acc[i][3]);
        float4 o1 = make_float4(acc[i][4], acc[i][5], acc[i][6], acc[i][7]);
        *(float4*)(O + row * H_ + tx * 8)     = o0;
        *(float4*)(O + row * H_ + tx * 8 + 4) = o1;
    }
}

// ---------------------------------------------------------------------------
// Flash attention (causal, single head):
// one thread = one query row; 128 query rows per block; K/V tiles (64x64 f32)
// staged in smem; online softmax with lazy rescale.
// grid = (T/128, B), block = 128.
// ---------------------------------------------------------------------------
__global__ __launch_bounds__(128) void attn_kernel(float* __restrict__ out)
{
    const int b   = blockIdx.y;
    // Reverse qt so heaviest (most keys) blocks launch first.
    const int qt  = (gridDim.x - 1 - blockIdx.x);
    const int q0  = qt * 128;
    const int tid = threadIdx.x;
    const int qi  = q0 + tid;

    __shared__ float Ks[64 * 64];
    __shared__ float Vs[64 * 64];

    // Load this thread's query row into registers
    float q[64];
    {
        const float4* qp = (const float4*)(g_q + ((size_t)b * T_ + qi) * H_);
#pragma unroll
        for (int c4 = 0; c4 < 16; c4++) {
            float4 v = qp[c4];
            q[c4 * 4 + 0] = v.x; q[c4 * 4 + 1] = v.y;
            q[c4 * 4 + 2] = v.z; q[c4 * 4 + 3] = v.w;
        }
    }

    float acc[64];
#pragma unroll
    for (int c = 0; c < 64; c++) acc[c] = 0.0f;
    float m = -INFINITY;
    float l = 0.0f;

    const int ktiles = (q0 + 128) / 64;   // tiles covering keys [0, q0+128)

    for (int kt = 0; kt < ktiles; kt++) {
        __syncthreads();   // previous tile fully consumed
        const int kbase = kt * 64;
        {
            const float4* Kp = (const float4*)(g_k + ((size_t)b * T_ + kbase) * H_);
            const float4* Vp = (const float4*)(g_v + ((size_t)b * T_ + kbase) * H_);
            float4* Ks4 = (float4*)Ks;
            float4* Vs4 = (float4*)Vs;
#pragma unroll
            for (int q8 = 0; q8 < 8; q8++) {
                int i = tid + 128 * q8;    // 0..1023 float4 slots
                Ks4[i] = Kp[i];
                Vs4[i] = Vp[i];
            }
        }
        __syncthreads();

        // Per-thread causal bound: keys kbase..kbase+jmax valid (jmax<0 => none)
        const int jmax = min(63, qi - kbase);

        for (int j = 0; j <= jmax; j++) {
            const float* kr = &Ks[j * 64];
            float s = 0.0f;
#pragma unroll
            for (int c = 0; c < 64; c += 4) {
                float4 kv = *(const float4*)(kr + c);   // broadcast across warp
                s += q[c + 0] * kv.x;
                s += q[c + 1] * kv.y;
                s += q[c + 2] * kv.z;
                s += q[c + 3] * kv.w;
            }
            s *= 0.125f;   // 1/sqrt(64)

            float mn = fmaxf(m, s);
            float p  = __expf(s - mn);
            if (mn > m) {
                float corr = __expf(m - mn);   // 0 on first valid key (m=-inf)
                l *= corr;
#pragma unroll
                for (int c = 0; c < 64; c++) acc[c] *= corr;
                m = mn;
            }
            l += p;

            const float* vr = &Vs[j * 64];
#pragma unroll
            for (int c = 0; c < 64; c += 4) {
                float4 vv = *(const float4*)(vr + c);   // broadcast
                acc[c + 0] += p * vv.x;
                acc[c + 1] += p * vv.y;
                acc[c + 2] += p * vv.z;
                acc[c + 3] += p * vv.w;
            }
        }
    }

    const float inv = 1.0f / l;
    float4* op = (float4*)(out + ((size_t)b * T_ + qi) * H_);
#pragma unroll
    for (int c4 = 0; c4 < 16; c4++) {
        float4 o;
        o.x = acc[c4 * 4 + 0] * inv;
        o.y = acc[c4 * 4 + 1] * inv;
        o.z = acc[c4 * 4 + 2] * inv;
        o.w = acc[c4 * 4 + 3] * inv;
        op[c4] = o;
    }
}

// ---------------------------------------------------------------------------
extern "C" void kernel_launch(void* const* d_in, const int* in_sizes, int n_in,
                              void* d_out, int out_size)
{
    const float* x  = (const float*)d_in[0];
    const float* wq = (const float*)d_in[1];
    const float* wk = (const float*)d_in[2];
    const float* wv = (const float*)d_in[3];
    float* out = (float*)d_out;

    dim3 pgrid(M_ / 64, 3);
    proj_kernel<<<pgrid, 128>>>(x, wq, wk, wv);

    dim3 agrid(T_ / 128, B_);
    attn_kernel<<<agrid, 128>>>(out);
}